// round 10
// baseline (speedup 1.0000x reference)
#include <cuda_runtime.h>
#include <cuda.h>
#include <cstddef>
#include <cstdint>

// HardDTW max-plus scan — R9 wavefront + TMA-store epilogue.
//
//   out[b,0,k] = x[b,0,k]
//   out[b,t,k] = x[b,t,k] + max(out[b,t-1,k], out[b,t-1,k-1])   (k-1 < 0 -> -inf)
//
// One CTA per batch (B=32), 256 threads (8 warps), thread owns 4 consecutive k.
// Warp w processes chunk c = e - w (16 steps) at epoch e; 1 __syncthreads per
// epoch; upstream edges via double-buffered smem. x via 16-deep LDG register
// queue (R9). CHANGE vs R9: per-step STG.128 (12-cyc LSU issue) is replaced by
// STS.128 into a per-warp staging slab + ONE 2D TMA store per chunk (8 KB,
// box [128 floats x 16 rows]); double-buffered, wait_group.read 1 before
// reuse. Theory: per-SM step cost is LSU/MIO instruction-issue bound
// (~26 cyc/warp-step); evicting STG cuts it to ~17.

namespace {
constexpr int T = 2048;
constexpr int K = 1024;
constexpr int THREADS = 256;
constexpr int NWARP = THREADS / 32;          // 8
constexpr int RS = K / 4;                    // float4 per row
constexpr int CHUNK = 16;
constexpr int D = 16;                        // prefetch depth == CHUNK
constexpr int NCHUNK = T / CHUNK;            // 128
constexpr int NEPOCH = NCHUNK + NWARP - 1;   // 135
// staging: [2 buf][8 warps][16 rows][128 floats] = 128 KB dynamic smem
constexpr int STAGE_F4_PER_WARP = CHUNK * 32;            // 512 float4
constexpr int STAGE_F4_PER_BUF  = NWARP * STAGE_F4_PER_WARP;
constexpr size_t SMEM_BYTES = 2u * STAGE_F4_PER_BUF * sizeof(float4);
}

// ───────────────────────── TMA-store kernel ─────────────────────────
__global__ __launch_bounds__(THREADS, 1)
void harddtw_tmast_kernel(const float* __restrict__ x,
                          const __grid_constant__ CUtensorMap tmap) {
    extern __shared__ float4 stag[];              // [2][NWARP][CHUNK][32]
    __shared__ float edges[2][NWARP][CHUNK];

    const int tid  = threadIdx.x;
    const int lane = tid & 31;
    const int warp = tid >> 5;
    const int b    = blockIdx.x;
    const float NEG_INF = __int_as_float(0xff800000);

    const float4* __restrict__ xr =
        reinterpret_cast<const float4*>(x + (size_t)b * T * K) + tid;

    const bool prod = (warp < NWARP - 1) && (lane == 31);
    const int pw = (warp == 0) ? 0 : (warp - 1);
    const int bl = (lane < CHUNK) ? lane : (CHUNK - 1);

    // Preload chunk 0 (rows 0..15).
    float4 xq[D];
#pragma unroll
    for (int j = 0; j < D; ++j) xq[j] = xr[(size_t)j * RS];

    float4 cur = make_float4(NEG_INF, NEG_INF, NEG_INF, NEG_INF);

    for (int e = 0; e < NEPOCH; ++e) {
        const int c = e - warp;
        if (0 <= c && c < NCHUNK) {
            const int t0 = c * CHUNK;
            const int buf = e & 1;

            // Ensure the TMA store that last read this buffer (2 epochs ago)
            // has completed its smem reads.
            if (lane == 0)
                asm volatile("cp.async.bulk.wait_group.read 1;" ::: "memory");
            __syncwarp();

            // Boundary vector from upstream warp (epoch e-1).
            float bv = edges[(e - 1) & 1][pw][bl];
            if (prod) edges[buf][warp][0] = cur.w;

            // Per-warp staging slab for this buffer.
            float4* sp = stag + (size_t)buf * STAGE_F4_PER_BUF
                              + (size_t)warp * STAGE_F4_PER_WARP + lane;

#pragma unroll
            for (int j = 0; j < CHUNK; ++j) {
                const float4 xv = xq[j];
                if (c + 1 < NCHUNK) xq[j] = xr[(size_t)(t0 + j + D) * RS];

                if (c == 0 && j == 0) {
                    cur = xv;  // init row: out[0] = x[0]
                } else {
                    float up = __shfl_up_sync(0xffffffffu, cur.w, 1);
                    const float bc = __shfl_sync(0xffffffffu, bv, j);
                    if (lane == 0) up = (warp == 0) ? NEG_INF : bc;

                    float4 n;
                    n.x = xv.x + fmaxf(cur.x, up);
                    n.y = xv.y + fmaxf(cur.y, cur.x);
                    n.z = xv.z + fmaxf(cur.z, cur.y);
                    n.w = xv.w + fmaxf(cur.w, cur.z);
                    cur = n;
                }

                sp[j * 32] = cur;                      // STS.128, immediate offset
                if (j < CHUNK - 1) {
                    if (prod) edges[buf][warp][j + 1] = cur.w;
                }
            }

            // Drain this warp's 16x512B slice to gmem with one 2D TMA store.
            __syncwarp();
            if (lane == 0) {
                asm volatile("fence.proxy.async.shared::cta;" ::: "memory");
                uint32_t saddr = (uint32_t)__cvta_generic_to_shared(
                    stag + (size_t)buf * STAGE_F4_PER_BUF
                         + (size_t)warp * STAGE_F4_PER_WARP);
                const int x0 = warp * 128;         // element coord in dim0 (K)
                const int y0 = b * T + t0;         // row coord in dim1 (B*T)
                asm volatile(
                    "cp.async.bulk.tensor.2d.global.shared::cta.tile.bulk_group "
                    "[%0, {%1, %2}], [%3];"
                    :: "l"(&tmap), "r"(x0), "r"(y0), "r"(saddr) : "memory");
                asm volatile("cp.async.bulk.commit_group;" ::: "memory");
            }
        }
        __syncthreads();
    }

    // Full drain before exit (gmem visibility).
    if (lane == 0)
        asm volatile("cp.async.bulk.wait_group 0;" ::: "memory");
}

// ───────────────────────── fallback: R9 kernel ─────────────────────────
__global__ __launch_bounds__(THREADS, 1)
void harddtw_wave16_kernel(const float* __restrict__ x, float* __restrict__ out) {
    __shared__ float edges[2][NWARP][CHUNK];

    const int tid  = threadIdx.x;
    const int lane = tid & 31;
    const int warp = tid >> 5;
    const int b    = blockIdx.x;
    const float NEG_INF = __int_as_float(0xff800000);

    const float4* __restrict__ xr =
        reinterpret_cast<const float4*>(x + (size_t)b * T * K) + tid;
    float4* __restrict__ orow =
        reinterpret_cast<float4*>(out + (size_t)b * T * K) + tid;

    const bool prod = (warp < NWARP - 1) && (lane == 31);
    const int pw = (warp == 0) ? 0 : (warp - 1);
    const int bl = (lane < CHUNK) ? lane : (CHUNK - 1);

    float4 xq[D];
#pragma unroll
    for (int j = 0; j < D; ++j) xq[j] = xr[(size_t)j * RS];

    float4 cur = make_float4(NEG_INF, NEG_INF, NEG_INF, NEG_INF);

    for (int e = 0; e < NEPOCH; ++e) {
        const int c = e - warp;
        if (0 <= c && c < NCHUNK) {
            const int t0 = c * CHUNK;
            float bv = edges[(e - 1) & 1][pw][bl];
            if (prod) edges[e & 1][warp][0] = cur.w;

#pragma unroll
            for (int j = 0; j < CHUNK; ++j) {
                const int t = t0 + j;
                const float4 xv = xq[j];
                if (c + 1 < NCHUNK) xq[j] = xr[(size_t)(t + D) * RS];

                if (c == 0 && j == 0) {
                    cur = xv;
                } else {
                    float up = __shfl_up_sync(0xffffffffu, cur.w, 1);
                    const float bc = __shfl_sync(0xffffffffu, bv, j);
                    if (lane == 0) up = (warp == 0) ? NEG_INF : bc;

                    float4 n;
                    n.x = xv.x + fmaxf(cur.x, up);
                    n.y = xv.y + fmaxf(cur.y, cur.x);
                    n.z = xv.z + fmaxf(cur.z, cur.y);
                    n.w = xv.w + fmaxf(cur.w, cur.z);
                    cur = n;
                }

                orow[(size_t)t * RS] = cur;
                if (j < CHUNK - 1) {
                    if (prod) edges[e & 1][warp][j + 1] = cur.w;
                }
            }
        }
        __syncthreads();
    }
}

// ───────────────────────── host ─────────────────────────
typedef CUresult (*PFN_EncodeTiled)(
    CUtensorMap*, CUtensorMapDataType, cuuint32_t, void*,
    const cuuint64_t*, const cuuint64_t*, const cuuint32_t*, const cuuint32_t*,
    CUtensorMapInterleave, CUtensorMapSwizzle, CUtensorMapL2promotion,
    CUtensorMapFloatOOBfill);

extern "C" void kernel_launch(void* const* d_in, const int* in_sizes, int n_in,
                              void* d_out, int out_size) {
    const float* x = (const float*)d_in[0];
    float* out = (float*)d_out;
    const int B = in_sizes[0] / (T * K);

    // Build the 2D tensormap for out: dims [K, B*T], box [128, 16], no swizzle.
    bool tma_ok = false;
    CUtensorMap tmap;
    {
        void* fp = nullptr;
        cudaDriverEntryPointQueryResult st;
        if (cudaGetDriverEntryPointByVersion("cuTensorMapEncodeTiled", &fp, 12000,
                                             cudaEnableDefault, &st) == cudaSuccess
            && fp && st == cudaDriverEntryPointSuccess) {
            PFN_EncodeTiled enc = (PFN_EncodeTiled)fp;
            cuuint64_t dims[2]    = {(cuuint64_t)K, (cuuint64_t)((size_t)B * T)};
            cuuint64_t strides[1] = {(cuuint64_t)K * sizeof(float)};
            cuuint32_t box[2]     = {128u, (cuuint32_t)CHUNK};
            cuuint32_t estr[2]    = {1u, 1u};
            CUresult r = enc(&tmap, CU_TENSOR_MAP_DATA_TYPE_FLOAT32, 2, out,
                             dims, strides, box, estr,
                             CU_TENSOR_MAP_INTERLEAVE_NONE,
                             CU_TENSOR_MAP_SWIZZLE_NONE,
                             CU_TENSOR_MAP_L2_PROMOTION_L2_128B,
                             CU_TENSOR_MAP_FLOAT_OOB_FILL_NONE);
            tma_ok = (r == CUDA_SUCCESS);
        }
    }

    if (tma_ok) {
        cudaFuncSetAttribute(harddtw_tmast_kernel,
                             cudaFuncAttributeMaxDynamicSharedMemorySize,
                             (int)SMEM_BYTES);
        harddtw_tmast_kernel<<<B, THREADS, SMEM_BYTES>>>(x, tmap);
    } else {
        harddtw_wave16_kernel<<<B, THREADS>>>(x, out);
    }
}

// round 11
// speedup vs baseline: 1.1198x; 1.1198x over previous
#include <cuda_runtime.h>
#include <cstddef>

// HardDTW max-plus scan — R9 wavefront with PAIRWISE named barriers.
//
//   out[b,0,k] = x[b,0,k]
//   out[b,t,k] = x[b,t,k] + max(out[b,t-1,k], out[b,t-1,k-1])   (k-1 < 0 -> -inf)
//
// One CTA per batch (B=32), 256 threads (8 warps), thread owns 4 consecutive k
// (float4 carry). Warp w processes chunk c = e - w (16 steps) at epoch e.
// CHANGE vs R9: the per-epoch __syncthreads (full-CTA coupling + HW store
// drain) is replaced by pairwise named barriers: warps w and w+1 share
// bar.sync id=w+1 (64 threads). Each warp syncs only with the neighbors it
// exchanges edges with; double-buffered edges give the same RAW/WAR ordering
// through the shared barrier. Everything else is R9 verbatim.

namespace {
constexpr int T = 2048;
constexpr int K = 1024;
constexpr int THREADS = 256;
constexpr int NWARP = THREADS / 32;          // 8
constexpr int RS = K / 4;                    // float4 per row
constexpr int CHUNK = 16;
constexpr int D = 16;                        // prefetch depth == CHUNK
constexpr int NCHUNK = T / CHUNK;            // 128
constexpr int NEPOCH = NCHUNK + NWARP - 1;   // 135
}

__global__ __launch_bounds__(THREADS, 1)
void harddtw_pair_kernel(const float* __restrict__ x, float* __restrict__ out) {
    // edges[p][w][j] : warp w's edge value at step t0+j-1 of the chunk it
    // processed in an epoch of parity p (slot 0 = carry entering the chunk).
    __shared__ float edges[2][NWARP][CHUNK];

    const int tid  = threadIdx.x;
    const int lane = tid & 31;
    const int warp = tid >> 5;
    const int b    = blockIdx.x;
    const float NEG_INF = __int_as_float(0xff800000);

    const float4* __restrict__ xr =
        reinterpret_cast<const float4*>(x + (size_t)b * T * K) + tid;
    float4* __restrict__ orow =
        reinterpret_cast<float4*>(out + (size_t)b * T * K) + tid;

    const bool prod = (warp < NWARP - 1) && (lane == 31);
    const int pw = (warp == 0) ? 0 : (warp - 1);   // safe upstream index
    const int bl = (lane < CHUNK) ? lane : (CHUNK - 1);

    // Preload chunk 0 (rows 0..15) into the rolling queue.
    float4 xq[D];
#pragma unroll
    for (int j = 0; j < D; ++j) xq[j] = xr[(size_t)j * RS];

    float4 cur = make_float4(NEG_INF, NEG_INF, NEG_INF, NEG_INF);

    for (int e = 0; e < NEPOCH; ++e) {
        const int c = e - warp;
        if (0 <= c && c < NCHUNK) {
            const int t0 = c * CHUNK;

            // Boundary vector from upstream warp (written during epoch e-1,
            // ordered by the shared pairwise barrier at end of epoch e-1).
            float bv = edges[(e - 1) & 1][pw][bl];

            // Publish slot 0: our carry entering this chunk (garbage at c==0,
            // never consumed there).
            if (prod) edges[e & 1][warp][0] = cur.w;

#pragma unroll
            for (int j = 0; j < CHUNK; ++j) {
                const int t = t0 + j;
                const float4 xv = xq[j];
                if (c + 1 < NCHUNK) xq[j] = xr[(size_t)(t + D) * RS];

                if (c == 0 && j == 0) {
                    cur = xv;  // init row: out[0] = x[0]
                } else {
                    float up = __shfl_up_sync(0xffffffffu, cur.w, 1);
                    const float bc = __shfl_sync(0xffffffffu, bv, j);
                    if (lane == 0) up = (warp == 0) ? NEG_INF : bc;

                    float4 n;
                    n.x = xv.x + fmaxf(cur.x, up);
                    n.y = xv.y + fmaxf(cur.y, cur.x);
                    n.z = xv.z + fmaxf(cur.z, cur.y);
                    n.w = xv.w + fmaxf(cur.w, cur.z);
                    cur = n;
                }

                orow[(size_t)t * RS] = cur;
                if (j < CHUNK - 1) {
                    if (prod) edges[e & 1][warp][j + 1] = cur.w;
                }
            }
        }

        // Pairwise producer/consumer sync (replaces __syncthreads):
        //   barrier id w+1 is shared by warps w and w+1 (64 threads).
        // Upstream first, then downstream: release cascades from warp 0,
        // no deadlock; every warp executes its barriers every epoch.
        if (warp > 0)
            asm volatile("bar.sync %0, 64;" :: "r"(warp) : "memory");
        if (warp < NWARP - 1)
            asm volatile("bar.sync %0, 64;" :: "r"(warp + 1) : "memory");
    }
}

extern "C" void kernel_launch(void* const* d_in, const int* in_sizes, int n_in,
                              void* d_out, int out_size) {
    const float* x = (const float*)d_in[0];
    float* out = (float*)d_out;
    const int B = in_sizes[0] / (T * K);
    harddtw_pair_kernel<<<B, THREADS>>>(x, out);
}

// round 12
// speedup vs baseline: 1.4756x; 1.3178x over previous
#include <cuda_runtime.h>
#include <cstddef>
#include <cstdint>

// HardDTW max-plus scan — R9 wavefront with cp.async-staged x tiles.
//
//   out[b,0,k] = x[b,0,k]
//   out[b,t,k] = x[b,t,k] + max(out[b,t-1,k], out[b,t-1,k-1])   (k-1 < 0 -> -inf)
//
// One CTA per batch (B=32), 256 threads (8 warps), thread owns 4 consecutive k
// (float4 carry). Warp w processes chunk c = e - w (16 steps) at epoch e; one
// __syncthreads per epoch; edges via double-buffered smem (R9 verbatim).
// CHANGE vs R9: the 16-deep LDG register queue (whose consumers rotate through
// only 6 scoreboard slots, collapsing effective prefetch depth) is replaced by
// cp.async into double-buffered per-warp smem tiles. Completion is tracked by
// commit_group/wait_group — no register scoreboards — and the inner loop reads
// x via LDS.128. Each thread reads exactly the 16B it wrote, so per-thread
// wait_group suffices with no extra synchronization.

namespace {
constexpr int T = 2048;
constexpr int K = 1024;
constexpr int THREADS = 256;
constexpr int NWARP = THREADS / 32;          // 8
constexpr int RS = K / 4;                    // float4 per row
constexpr int CHUNK = 16;
constexpr int NCHUNK = T / CHUNK;            // 128
constexpr int NEPOCH = NCHUNK + NWARP - 1;   // 135
constexpr int ROW_BYTES = 32 * 16;           // 512 B per warp-row
constexpr int SLAB = CHUNK * ROW_BYTES;      // 8 KB per warp per buffer
constexpr size_t SMEM_BYTES = 2u * NWARP * SLAB;   // 128 KB
}

__global__ __launch_bounds__(THREADS, 1)
void harddtw_cpasync_kernel(const float* __restrict__ x,
                            float* __restrict__ out) {
    extern __shared__ char xs[];               // [2][NWARP][CHUNK][512B]
    __shared__ float edges[2][NWARP][CHUNK];

    const int tid  = threadIdx.x;
    const int lane = tid & 31;
    const int warp = tid >> 5;
    const int b    = blockIdx.x;
    const float NEG_INF = __int_as_float(0xff800000);

    // gmem base for this thread's 16B column slice; row r at +r*4096 bytes.
    const char* gbase = reinterpret_cast<const char*>(
        x + (size_t)b * T * K + warp * 128 + lane * 4);
    float4* __restrict__ orow =
        reinterpret_cast<float4*>(out + (size_t)b * T * K) + tid;

    // smem slab addresses (32-bit shared-window offsets for cp.async).
    const uint32_t s0 = (uint32_t)__cvta_generic_to_shared(xs)
                        + (uint32_t)(warp * SLAB) + (uint32_t)(lane * 16);
    const uint32_t s1 = s0 + (uint32_t)(NWARP * SLAB);

    const bool prod = (warp < NWARP - 1) && (lane == 31);
    const int pw = (warp == 0) ? 0 : (warp - 1);
    const int bl = (lane < CHUNK) ? lane : (CHUNK - 1);

    // Prologue: stage chunk 0 into buffer 0.
#pragma unroll
    for (int j = 0; j < CHUNK; ++j) {
        asm volatile("cp.async.cg.shared.global [%0], [%1], 16;"
                     :: "r"(s0 + j * ROW_BYTES),
                        "l"(gbase + (size_t)j * 4096) : "memory");
    }
    asm volatile("cp.async.commit_group;" ::: "memory");

    float4 cur = make_float4(NEG_INF, NEG_INF, NEG_INF, NEG_INF);

    for (int e = 0; e < NEPOCH; ++e) {
        const int c = e - warp;
        if (0 <= c && c < NCHUNK) {
            const int t0 = c * CHUNK;
            const uint32_t scur = (c & 1) ? s1 : s0;
            const uint32_t snxt = (c & 1) ? s0 : s1;

            // Stage chunk c+1 (group N+1); then wait until only that group is
            // outstanding, i.e. chunk c's tile is resident.
            if (c + 1 < NCHUNK) {
                const char* gn = gbase + (size_t)(t0 + CHUNK) * 4096;
#pragma unroll
                for (int j = 0; j < CHUNK; ++j) {
                    asm volatile("cp.async.cg.shared.global [%0], [%1], 16;"
                                 :: "r"(snxt + j * ROW_BYTES),
                                    "l"(gn + (size_t)j * 4096) : "memory");
                }
            }
            asm volatile("cp.async.commit_group;" ::: "memory");
            asm volatile("cp.async.wait_group 1;" ::: "memory");

            // Boundary vector from upstream warp (written during epoch e-1).
            float bv = edges[(e - 1) & 1][pw][bl];

            // Publish slot 0: carry entering this chunk (garbage at c==0, unused).
            if (prod) edges[e & 1][warp][0] = cur.w;

#pragma unroll
            for (int j = 0; j < CHUNK; ++j) {
                const int t = t0 + j;
                float4 xv;
                {
                    const uint32_t a = scur + j * ROW_BYTES;
                    asm volatile("ld.shared.v4.f32 {%0,%1,%2,%3}, [%4];"
                                 : "=f"(xv.x), "=f"(xv.y), "=f"(xv.z), "=f"(xv.w)
                                 : "r"(a));
                }

                if (c == 0 && j == 0) {
                    cur = xv;  // init row: out[0] = x[0]
                } else {
                    float up = __shfl_up_sync(0xffffffffu, cur.w, 1);
                    const float bc = __shfl_sync(0xffffffffu, bv, j);
                    if (lane == 0) up = (warp == 0) ? NEG_INF : bc;

                    float4 n;
                    n.x = xv.x + fmaxf(cur.x, up);
                    n.y = xv.y + fmaxf(cur.y, cur.x);
                    n.z = xv.z + fmaxf(cur.z, cur.y);
                    n.w = xv.w + fmaxf(cur.w, cur.z);
                    cur = n;
                }

                orow[(size_t)t * RS] = cur;
                if (j < CHUNK - 1) {
                    if (prod) edges[e & 1][warp][j + 1] = cur.w;
                }
            }
        }
        __syncthreads();
    }
}

extern "C" void kernel_launch(void* const* d_in, const int* in_sizes, int n_in,
                              void* d_out, int out_size) {
    const float* x = (const float*)d_in[0];
    float* out = (float*)d_out;
    const int B = in_sizes[0] / (T * K);
    cudaFuncSetAttribute(harddtw_cpasync_kernel,
                         cudaFuncAttributeMaxDynamicSharedMemorySize,
                         (int)SMEM_BYTES);
    harddtw_cpasync_kernel<<<B, THREADS, SMEM_BYTES>>>(x, out);
}